// round 14
// baseline (speedup 1.0000x reference)
#include <cuda_runtime.h>
#include <math.h>
#include <stdint.h>

// ---------------- problem constants ----------------
#define S_LEN 2048
#define D_DIM 1024
#define B_DIM 2
#define H_DIM 16
#define DK    64
#define F_DIM 4096
#define M_ROWS (B_DIM * S_LEN)   // 4096

// ---------------- scratch (static device globals; no allocation) -----------
__device__ __align__(256) float g_qb[M_ROWS * D_DIM];
__device__ __align__(256) float g_kb[M_ROWS * D_DIM];
__device__ __align__(256) float g_vb[M_ROWS * D_DIM];
__device__ __align__(256) float g_kT[B_DIM * H_DIM * DK * S_LEN];  // [b,h,c,j]
__device__ __align__(256) float g_concat[M_ROWS * D_DIM];
__device__ __align__(256) float g_q2[M_ROWS * D_DIM];
__device__ __align__(256) float g_x1[M_ROWS * D_DIM];
__device__ __align__(256) float g_h1[M_ROWS * F_DIM];
__device__ __align__(256) float g_ff[M_ROWS * D_DIM];

template <int ID>
__device__ __forceinline__ float* gsel(float* ext) {
    if (ID == 0) return g_qb;
    if (ID == 1) return g_kb;
    if (ID == 2) return g_vb;
    if (ID == 3) return g_concat;
    if (ID == 4) return g_q2;
    if (ID == 5) return g_x1;
    if (ID == 6) return g_h1;
    if (ID == 7) return g_ff;
    return ext;
}

// ---------------- fallback ----------------
__global__ void zero_out_k(float* out, long n) {
    long idx = (long)blockIdx.x * blockDim.x + threadIdx.x;
    for (; idx < n; idx += (long)gridDim.x * blockDim.x) out[idx] = 0.f;
}

// ================= GEMM v4: NO SHARED MEMORY, NO SYNCTHREADS ===============
// C[M,N] = A[M,K] @ W[N,K]^T + bias (+ReLU).
// Warp tile 8x8 (proven), lane-split K via float4 (chunk = 128),
// double-buffered prefetch. NEW: 512 threads / 16 warps as 4x4 ->
// 32-row x 32-col block tile: W L2 traffic halves (grid.y halves), and
// A row-slices are shared by 4 warps through L1.
template <int RELU, int AID, int CID, int KT>
__global__ void __launch_bounds__(512) gemm_v4(
    const float* __restrict__ Aext, const float* __restrict__ Wm,
    const float* __restrict__ bias, float* __restrict__ Cext,
    int M, int N)
{
    const float* A = gsel<AID>((float*)Aext);
    float* C = gsel<CID>(Cext);

    const int tid  = threadIdx.x;
    const int warp = tid >> 5;
    const int lane = tid & 31;
    const int wr = warp >> 2;               // 0..3
    const int wc = warp & 3;                // 0..3
    const int r0 = blockIdx.y * 32 + wr * 8;
    const int c0 = blockIdx.x * 32 + wc * 8;

    const float* Ab = A + (long)r0 * KT + lane * 4;
    const float* Wb = Wm + (long)c0 * KT + lane * 4;

    float acc[8][8];
#pragma unroll
    for (int r = 0; r < 8; r++)
#pragma unroll
        for (int c = 0; c < 8; c++) acc[r][c] = 0.f;

    float4 aC[8], wC[8];
#pragma unroll
    for (int r = 0; r < 8; r++) aC[r] = *(const float4*)(Ab + (long)r * KT);
#pragma unroll
    for (int c = 0; c < 8; c++) wC[c] = *(const float4*)(Wb + (long)c * KT);

#pragma unroll 2
    for (int k0 = 128; k0 <= KT; k0 += 128) {
        float4 aN[8], wN[8];
        const bool more = (k0 < KT);
        if (more) {
#pragma unroll
            for (int r = 0; r < 8; r++)
                aN[r] = *(const float4*)(Ab + (long)r * KT + k0);
#pragma unroll
            for (int c = 0; c < 8; c++)
                wN[c] = *(const float4*)(Wb + (long)c * KT + k0);
        }
#pragma unroll
        for (int r = 0; r < 8; r++)
#pragma unroll
            for (int c = 0; c < 8; c++) {
                float t = acc[r][c];
                t = fmaf(aC[r].x, wC[c].x, t);
                t = fmaf(aC[r].y, wC[c].y, t);
                t = fmaf(aC[r].z, wC[c].z, t);
                t = fmaf(aC[r].w, wC[c].w, t);
                acc[r][c] = t;
            }
        if (more) {
#pragma unroll
            for (int r = 0; r < 8; r++) aC[r] = aN[r];
#pragma unroll
            for (int c = 0; c < 8; c++) wC[c] = wN[c];
        }
    }

    // reduce the 64 accumulators across the warp (shfl only)
#pragma unroll
    for (int r = 0; r < 8; r++)
#pragma unroll
        for (int c = 0; c < 8; c++) {
#pragma unroll
            for (int o = 16; o; o >>= 1)
                acc[r][c] += __shfl_xor_sync(0xffffffffu, acc[r][c], o);
        }

    // lane l writes outputs o = l and o = l+32  (o = r*8 + c)
#pragma unroll
    for (int u = 0; u < 2; u++) {
        int o = lane + 32 * u;
        int r = o >> 3, c = o & 7;
        float x = acc[r][c] + bias[c0 + c];
        if (RELU) x = fmaxf(x, 0.f);
        C[(long)(r0 + r) * N + c0 + c] = x;
    }
}

// ================= K transpose: g_kb[b,j,(h,c)] -> g_kT[b,h,c,j] ===========
__global__ void __launch_bounds__(256) ktrans_kernel()
{
    const int j  = blockIdx.x * 256 + threadIdx.x;
    const int c  = blockIdx.y;
    const int bh = blockIdx.z;
    const int b = bh >> 4, h = bh & 15;
    float v = g_kb[(long)b * S_LEN * D_DIM + (long)j * D_DIM + h * DK + c];
    g_kT[((long)bh * DK + c) * S_LEN + j] = v;
}

// ================= ATTENTION v2 (unchanged from passing R13) ===============
__global__ void __launch_bounds__(256) attn_v2(
    const float* __restrict__ gammas, int mask_val)
{
    const int tid  = threadIdx.x;
    const int warp = tid >> 5;
    const int lane = tid & 31;
    const int i = blockIdx.x * 8 + warp;
    const int h = blockIdx.y;
    const int b = blockIdx.z;

    const int L = min(S_LEN, i + mask_val);
    const int nch = (L + 31) >> 5;

    const float* kT = g_kT + (long)(b * H_DIM + h) * DK * S_LEN;
    const long qoff = (long)b * S_LEN * D_DIM + (long)i * D_DIM + h * DK;

    float q[DK];
#pragma unroll
    for (int c = 0; c < DK; c++) q[c] = g_qb[qoff + c];

    float sl[S_LEN / 32];

    for (int ch = 0; ch < nch; ch++) {
        const int j = ch * 32 + lane;
        float acc = 0.f;
#pragma unroll
        for (int c = 0; c < DK; c++)
            acc = fmaf(q[c], kT[(long)c * S_LEN + j], acc);
        sl[ch] = (j < L) ? acc * 0.125f : -INFINITY;
    }

    float m1 = -INFINITY;
    for (int ch = 0; ch < nch; ch++) m1 = fmaxf(m1, sl[ch]);
#pragma unroll
    for (int o = 16; o; o >>= 1) m1 = fmaxf(m1, __shfl_xor_sync(0xffffffffu, m1, o));
    float zs = 0.f;
    for (int ch = 0; ch < nch; ch++) zs += __expf(sl[ch] - m1);
#pragma unroll
    for (int o = 16; o; o >>= 1) zs += __shfl_xor_sync(0xffffffffu, zs, o);
    const float Zinv = 1.f / zs;

    const float gv = gammas[h];
    const float gamma = -(gv > 20.f ? gv : log1pf(__expf(gv)));
    float running = 0.f;
    float m2 = -INFINITY;
    for (int ch = 0; ch < nch; ch++) {
        float p = __expf(sl[ch] - m1);
        float incl = p;
#pragma unroll
        for (int o = 1; o < 32; o <<= 1) {
            float t = __shfl_up_sync(0xffffffffu, incl, o);
            if (lane >= o) incl += t;
        }
        const int j = ch * 32 + lane;
        float sd = -INFINITY;
        if (j < L) {
            float ctot = (running + incl) * Zinv;
            float pe = fabsf((float)(i - j));
            float ds = sqrtf(fmaxf((1.f - ctot) * pe, 0.f));
            float te = fmaxf(__expf(gamma * ds), 1e-5f);
            sd = sl[ch] * te;
        }
        sl[ch] = sd;
        m2 = fmaxf(m2, sd);
        running += __shfl_sync(0xffffffffu, incl, 31);
    }

#pragma unroll
    for (int o = 16; o; o >>= 1) m2 = fmaxf(m2, __shfl_xor_sync(0xffffffffu, m2, o));
    float z2 = 0.f;
    for (int ch = 0; ch < nch; ch++) z2 += __expf(sl[ch] - m2);
#pragma unroll
    for (int o = 16; o; o >>= 1) z2 += __shfl_xor_sync(0xffffffffu, z2, o);
    const float Z2inv = 1.f / z2;

    const float* Vb = g_vb + (long)b * S_LEN * D_DIM + h * DK;
    float ov0 = 0.f, ov1 = 0.f;
    for (int ch = 0; ch < nch; ch++) {
        float wl = __expf(sl[ch] - m2) * Z2inv;
#pragma unroll 8
        for (int jj = 0; jj < 32; jj++) {
            float wj = __shfl_sync(0xffffffffu, wl, jj);
            const float* vr = Vb + (long)(ch * 32 + jj) * D_DIM;
            ov0 = fmaf(wj, vr[lane], ov0);
            ov1 = fmaf(wj, vr[lane + 32], ov1);
        }
    }

    g_concat[(long)(b * S_LEN + i) * D_DIM + h * DK + lane]      = ov0;
    g_concat[(long)(b * S_LEN + i) * D_DIM + h * DK + lane + 32] = ov1;
}

// ============ residual add + LayerNorm (unchanged) =========================
template <int XID, int YID, int OID>
__global__ void __launch_bounds__(256) add_ln_ns(
    const float* __restrict__ Xext, const float* __restrict__ Yext,
    const float* __restrict__ w, const float* __restrict__ bias,
    float* __restrict__ Oext)
{
    const float* X = gsel<XID>((float*)Xext);
    const float* Y = gsel<YID>((float*)Yext);
    float* out = gsel<OID>(Oext);

    const int tid  = threadIdx.x;
    const int warp = tid >> 5;
    const int lane = tid & 31;
    const int row = blockIdx.x * 8 + warp;

    float xv[D_DIM / 32];
    float lsum = 0.f;
#pragma unroll
    for (int u = 0; u < D_DIM / 32; u++) {
        int c = lane + 32 * u;
        float v = X[(long)row * D_DIM + c] + Y[(long)row * D_DIM + c];
        xv[u] = v;
        lsum += v;
    }
#pragma unroll
    for (int o = 16; o; o >>= 1) lsum += __shfl_xor_sync(0xffffffffu, lsum, o);
    const float mu = lsum / (float)D_DIM;

    float lvar = 0.f;
#pragma unroll
    for (int u = 0; u < D_DIM / 32; u++) {
        float d = xv[u] - mu;
        lvar += d * d;
    }
#pragma unroll
    for (int o = 16; o; o >>= 1) lvar += __shfl_xor_sync(0xffffffffu, lvar, o);
    const float inv = rsqrtf(lvar / (float)D_DIM + 1e-5f);

#pragma unroll
    for (int u = 0; u < D_DIM / 32; u++) {
        int c = lane + 32 * u;
        out[(long)row * D_DIM + c] = (xv[u] - mu) * inv * w[c] + bias[c];
    }
}

// ---------------- launch ----------------
extern "C" void kernel_launch(void* const* d_in, const int* in_sizes, int n_in,
                              void* d_out, int out_size)
{
    float* out = (float*)d_out;

    const long exp_sizes[18] = {
        (long)M_ROWS * D_DIM, (long)M_ROWS * D_DIM, (long)M_ROWS * D_DIM,
        (long)D_DIM * D_DIM, D_DIM,
        (long)D_DIM * D_DIM, D_DIM,
        (long)D_DIM * D_DIM, D_DIM,
        H_DIM,
        D_DIM, D_DIM,
        (long)F_DIM * D_DIM, F_DIM,
        (long)D_DIM * F_DIM, D_DIM,
        D_DIM, D_DIM
    };

    bool ok_e = (n_in >= 18), ok_b = (n_in >= 18);
    for (int idx = 0; idx < 18 && (ok_e || ok_b); idx++) {
        if ((long)in_sizes[idx] != exp_sizes[idx])     ok_e = false;
        if ((long)in_sizes[idx] != exp_sizes[idx] * 4) ok_b = false;
    }
    bool ok = (ok_e || ok_b) &&
              ((long)out_size == (long)M_ROWS * D_DIM ||
               (long)out_size == (long)M_ROWS * D_DIM * 4);
    if (ok) {
        for (int idx = 0; idx < 18; idx++)
            if (((uintptr_t)d_in[idx] & 15u) != 0) { ok = false; break; }
        if (((uintptr_t)d_out & 15u) != 0) ok = false;
    }
    if (!ok) {
        long n = (long)M_ROWS * D_DIM;
        if ((long)out_size < n) n = (long)out_size;
        zero_out_k<<<1024, 256>>>(out, n);
        return;
    }

    const float* query  = (const float*)d_in[0];
    const float* key    = (const float*)d_in[1];
    const float* values = (const float*)d_in[2];
    const float* Wk     = (const float*)d_in[3];
    const float* bk     = (const float*)d_in[4];
    const float* Wv     = (const float*)d_in[5];
    const float* bv     = (const float*)d_in[6];
    const float* Wo     = (const float*)d_in[7];
    const float* bo     = (const float*)d_in[8];
    const float* gammas = (const float*)d_in[9];
    const float* ln1_w  = (const float*)d_in[10];
    const float* ln1_b  = (const float*)d_in[11];
    const float* W1     = (const float*)d_in[12];
    const float* b1     = (const float*)d_in[13];
    const float* W2     = (const float*)d_in[14];
    const float* b2     = (const float*)d_in[15];
    const float* ln2_w  = (const float*)d_in[16];
    const float* ln2_b  = (const float*)d_in[17];

    // mask: python scalar (value 1). NEVER dereference; decode from pointer
    // value only if it is a tiny immediate.
    int mask_val = 1;
    if (n_in >= 19) {
        uintptr_t v = (uintptr_t)d_in[18];
        if (v >= 1 && v < 4096) mask_val = (int)v;
    }

    dim3 gD(D_DIM / 32, M_ROWS / 32);   // (32, 128)
    dim3 gF(F_DIM / 32, M_ROWS / 32);   // (128, 128)

    // q/k/v projections (kq_same: q and k both use Wk)
    gemm_v4<0, -1, 0, D_DIM><<<gD, 512>>>(query,  Wk, bk, nullptr, M_ROWS, D_DIM);
    gemm_v4<0, -1, 1, D_DIM><<<gD, 512>>>(key,    Wk, bk, nullptr, M_ROWS, D_DIM);
    gemm_v4<0, -1, 2, D_DIM><<<gD, 512>>>(values, Wv, bv, nullptr, M_ROWS, D_DIM);

    // transpose K per head for coalesced attention reads
    dim3 gT(S_LEN / 256, DK, B_DIM * H_DIM);
    ktrans_kernel<<<gT, 256>>>();

    // attention with distance decay (warp per row, coalesced)
    dim3 gA(S_LEN / 8, H_DIM, B_DIM);
    attn_v2<<<gA, 256>>>(gammas, mask_val);

    // output projection + LN1
    gemm_v4<0, 3, 4, D_DIM><<<gD, 512>>>(nullptr, Wo, bo, nullptr, M_ROWS, D_DIM);
    add_ln_ns<-1, 4, 5><<<M_ROWS / 8, 256>>>(query, nullptr, ln1_w, ln1_b, nullptr);

    // FFN + LN2 (final output to d_out)
    gemm_v4<1, 5, 6, D_DIM><<<gF, 512>>>(nullptr, W1, b1, nullptr, M_ROWS, F_DIM);
    gemm_v4<0, 6, 7, F_DIM><<<gD, 512>>>(nullptr, W2, b2, nullptr, M_ROWS, D_DIM);
    add_ln_ns<5, 7, -1><<<M_ROWS / 8, 256>>>(nullptr, nullptr, ln2_w, ln2_b, out);
}

// round 15
// speedup vs baseline: 10.1312x; 10.1312x over previous
#include <cuda_runtime.h>
#include <math.h>
#include <stdint.h>

// ---------------- problem constants ----------------
#define S_LEN 2048
#define D_DIM 1024
#define B_DIM 2
#define H_DIM 16
#define DK    64
#define F_DIM 4096
#define M_ROWS (B_DIM * S_LEN)   // 4096

// ---------------- scratch (static device globals; no allocation) -----------
__device__ __align__(256) float g_qb[M_ROWS * D_DIM];
__device__ __align__(256) float g_kb[M_ROWS * D_DIM];
__device__ __align__(256) float g_vb[M_ROWS * D_DIM];
__device__ __align__(256) float g_kT[B_DIM * H_DIM * DK * S_LEN];  // [b,h,c,j]
__device__ __align__(256) float g_vT[B_DIM * H_DIM * DK * S_LEN];  // [b,h,c,j]
__device__ __align__(256) float g_concat[M_ROWS * D_DIM];
__device__ __align__(256) float g_q2[M_ROWS * D_DIM];
__device__ __align__(256) float g_x1[M_ROWS * D_DIM];
__device__ __align__(256) float g_h1[M_ROWS * F_DIM];
__device__ __align__(256) float g_ff[M_ROWS * D_DIM];

template <int ID>
__device__ __forceinline__ float* gsel(float* ext) {
    if (ID == 0) return g_qb;
    if (ID == 1) return g_kb;
    if (ID == 2) return g_vb;
    if (ID == 3) return g_concat;
    if (ID == 4) return g_q2;
    if (ID == 5) return g_x1;
    if (ID == 6) return g_h1;
    if (ID == 7) return g_ff;
    return ext;
}

// ---------------- fallback ----------------
__global__ void zero_out_k(float* out, long n) {
    long idx = (long)blockIdx.x * blockDim.x + threadIdx.x;
    for (; idx < n; idx += (long)gridDim.x * blockDim.x) out[idx] = 0.f;
}

// ================= GEMM v3 (256 threads — the PROVEN R12/R13 version) ======
// NOTE R14 lesson: 512 threads forced regs<=128 -> accumulator spills -> 15x
// regression. 256 threads leaves 255 regs. DO NOT raise thread count here.
template <int RELU, int AID, int CID, int KT>
__global__ void __launch_bounds__(256) gemm_v3(
    const float* __restrict__ Aext, const float* __restrict__ Wm,
    const float* __restrict__ bias, float* __restrict__ Cext,
    int M, int N)
{
    const float* A = gsel<AID>((float*)Aext);
    float* C = gsel<CID>(Cext);

    const int tid  = threadIdx.x;
    const int warp = tid >> 5;
    const int lane = tid & 31;
    const int wr = warp >> 2;
    const int wc = warp & 3;
    const int r0 = blockIdx.y * 16 + wr * 8;
    const int c0 = blockIdx.x * 32 + wc * 8;

    const float* Ab = A + (long)r0 * KT + lane * 4;
    const float* Wb = Wm + (long)c0 * KT + lane * 4;

    float acc[8][8];
#pragma unroll
    for (int r = 0; r < 8; r++)
#pragma unroll
        for (int c = 0; c < 8; c++) acc[r][c] = 0.f;

    float4 aC[8], wC[8];
#pragma unroll
    for (int r = 0; r < 8; r++) aC[r] = *(const float4*)(Ab + (long)r * KT);
#pragma unroll
    for (int c = 0; c < 8; c++) wC[c] = *(const float4*)(Wb + (long)c * KT);

#pragma unroll 2
    for (int k0 = 128; k0 <= KT; k0 += 128) {
        float4 aN[8], wN[8];
        const bool more = (k0 < KT);
        if (more) {
#pragma unroll
            for (int r = 0; r < 8; r++)
                aN[r] = *(const float4*)(Ab + (long)r * KT + k0);
#pragma unroll
            for (int c = 0; c < 8; c++)
                wN[c] = *(const float4*)(Wb + (long)c * KT + k0);
        }
#pragma unroll
        for (int r = 0; r < 8; r++)
#pragma unroll
            for (int c = 0; c < 8; c++) {
                float t = acc[r][c];
                t = fmaf(aC[r].x, wC[c].x, t);
                t = fmaf(aC[r].y, wC[c].y, t);
                t = fmaf(aC[r].z, wC[c].z, t);
                t = fmaf(aC[r].w, wC[c].w, t);
                acc[r][c] = t;
            }
        if (more) {
#pragma unroll
            for (int r = 0; r < 8; r++) aC[r] = aN[r];
#pragma unroll
            for (int c = 0; c < 8; c++) wC[c] = wN[c];
        }
    }

#pragma unroll
    for (int r = 0; r < 8; r++)
#pragma unroll
        for (int c = 0; c < 8; c++) {
#pragma unroll
            for (int o = 16; o; o >>= 1)
                acc[r][c] += __shfl_xor_sync(0xffffffffu, acc[r][c], o);
        }

#pragma unroll
    for (int u = 0; u < 2; u++) {
        int o = lane + 32 * u;
        int r = o >> 3, c = o & 7;
        float x = acc[r][c] + bias[c0 + c];
        if (RELU) x = fmaxf(x, 0.f);
        C[(long)(r0 + r) * N + c0 + c] = x;
    }
}

// ============ head-transpose: src[b,j,(h,c)] -> dst[b,h,c,j] ===============
// SRC = 1 -> g_kb -> g_kT ;  SRC = 2 -> g_vb -> g_vT
template <int SRC>
__global__ void __launch_bounds__(256) htrans_kernel()
{
    const int j  = blockIdx.x * 256 + threadIdx.x;
    const int c  = blockIdx.y;
    const int bh = blockIdx.z;
    const int b = bh >> 4, h = bh & 15;
    const float* src = (SRC == 1) ? g_kb : g_vb;
    float* dst = (SRC == 1) ? g_kT : g_vT;
    float v = src[(long)b * S_LEN * D_DIM + (long)j * D_DIM + h * DK + c];
    dst[((long)bh * DK + c) * S_LEN + j] = v;
}

// ================= ATTENTION v3: fully coalesced, shfl-light ===============
// One warp per (query row i, head h, batch b). Lane owns j = chunk*32+lane.
// K and V both in [b,h,c,j] layout: every load is one 128B line per warp.
// AV pass: each lane accumulates partials for ALL 64 out dims over its own
// j's (no per-j shfl broadcast); one 64x5-shfl reduction at the end.
__global__ void __launch_bounds__(256) attn_v3(
    const float* __restrict__ gammas, int mask_val)
{
    const int tid  = threadIdx.x;
    const int warp = tid >> 5;
    const int lane = tid & 31;
    const int i = blockIdx.x * 8 + warp;
    const int h = blockIdx.y;
    const int b = blockIdx.z;

    const int L = min(S_LEN, i + mask_val);
    const int nch = (L + 31) >> 5;

    const float* kT = g_kT + (long)(b * H_DIM + h) * DK * S_LEN;
    const float* vT = g_vT + (long)(b * H_DIM + h) * DK * S_LEN;
    const long qoff = (long)b * S_LEN * D_DIM + (long)i * D_DIM + h * DK;

    float q[DK];
#pragma unroll
    for (int c = 0; c < DK; c++) q[c] = g_qb[qoff + c];

    float sl[S_LEN / 32];   // ordered scores: sl[ch] is j = ch*32+lane

    // ---- pass 1: scores (coalesced K reads) ----
    for (int ch = 0; ch < nch; ch++) {
        const int j = ch * 32 + lane;
        float acc = 0.f;
#pragma unroll
        for (int c = 0; c < DK; c++)
            acc = fmaf(q[c], kT[(long)c * S_LEN + j], acc);
        sl[ch] = (j < L) ? acc * 0.125f : -INFINITY;   // 1/sqrt(64)
    }

    // ---- softmax #1 stats ----
    float m1 = -INFINITY;
    for (int ch = 0; ch < nch; ch++) m1 = fmaxf(m1, sl[ch]);
#pragma unroll
    for (int o = 16; o; o >>= 1) m1 = fmaxf(m1, __shfl_xor_sync(0xffffffffu, m1, o));
    float zs = 0.f;
    for (int ch = 0; ch < nch; ch++) zs += __expf(sl[ch] - m1);
#pragma unroll
    for (int o = 16; o; o >>= 1) zs += __shfl_xor_sync(0xffffffffu, zs, o);
    const float Zinv = 1.f / zs;

    // ---- pass 2: ordered cumsum + distance decay ----
    const float gv = gammas[h];
    const float gamma = -(gv > 20.f ? gv : log1pf(__expf(gv)));  // -softplus<0
    float running = 0.f;
    float m2 = -INFINITY;
    for (int ch = 0; ch < nch; ch++) {
        float p = __expf(sl[ch] - m1);
        float incl = p;
#pragma unroll
        for (int o = 1; o < 32; o <<= 1) {
            float t = __shfl_up_sync(0xffffffffu, incl, o);
            if (lane >= o) incl += t;
        }
        const int j = ch * 32 + lane;
        float sd = -INFINITY;
        if (j < L) {
            float ctot = (running + incl) * Zinv;
            float pe = fabsf((float)(i - j));
            float ds = sqrtf(fmaxf((1.f - ctot) * pe, 0.f));
            float te = fmaxf(__expf(gamma * ds), 1e-5f);
            sd = sl[ch] * te;
        }
        sl[ch] = sd;
        m2 = fmaxf(m2, sd);
        running += __shfl_sync(0xffffffffu, incl, 31);
    }

    // ---- softmax #2 stats ----
#pragma unroll
    for (int o = 16; o; o >>= 1) m2 = fmaxf(m2, __shfl_xor_sync(0xffffffffu, m2, o));
    float z2 = 0.f;
    for (int ch = 0; ch < nch; ch++) z2 += __expf(sl[ch] - m2);
#pragma unroll
    for (int o = 16; o; o >>= 1) z2 += __shfl_xor_sync(0xffffffffu, z2, o);
    const float Z2inv = 1.f / z2;

    // ---- pass 3: out = attn @ V, per-lane partials over own j's ----
    float ov[DK];
#pragma unroll
    for (int c = 0; c < DK; c++) ov[c] = 0.f;
    for (int ch = 0; ch < nch; ch++) {
        const int j = ch * 32 + lane;
        const float wl = __expf(sl[ch] - m2) * Z2inv;   // 0 for j >= L
#pragma unroll
        for (int c = 0; c < DK; c++)
            ov[c] = fmaf(wl, vT[(long)c * S_LEN + j], ov[c]);
    }
#pragma unroll
    for (int c = 0; c < DK; c++) {
#pragma unroll
        for (int o = 16; o; o >>= 1)
            ov[c] += __shfl_xor_sync(0xffffffffu, ov[c], o);
    }

    g_concat[(long)(b * S_LEN + i) * D_DIM + h * DK + lane]      = ov[lane];
    g_concat[(long)(b * S_LEN + i) * D_DIM + h * DK + lane + 32] = ov[lane + 32];
}

// ============ residual add + LayerNorm (unchanged) =========================
template <int XID, int YID, int OID>
__global__ void __launch_bounds__(256) add_ln_ns(
    const float* __restrict__ Xext, const float* __restrict__ Yext,
    const float* __restrict__ w, const float* __restrict__ bias,
    float* __restrict__ Oext)
{
    const float* X = gsel<XID>((float*)Xext);
    const float* Y = gsel<YID>((float*)Yext);
    float* out = gsel<OID>(Oext);

    const int tid  = threadIdx.x;
    const int warp = tid >> 5;
    const int lane = tid & 31;
    const int row = blockIdx.x * 8 + warp;

    float xv[D_DIM / 32];
    float lsum = 0.f;
#pragma unroll
    for (int u = 0; u < D_DIM / 32; u++) {
        int c = lane + 32 * u;
        float v = X[(long)row * D_DIM + c] + Y[(long)row * D_DIM + c];
        xv[u] = v;
        lsum += v;
    }
#pragma unroll
    for (int o = 16; o; o >>= 1) lsum += __shfl_xor_sync(0xffffffffu, lsum, o);
    const float mu = lsum / (float)D_DIM;

    float lvar = 0.f;
#pragma unroll
    for (int u = 0; u < D_DIM / 32; u++) {
        float d = xv[u] - mu;
        lvar += d * d;
    }
#pragma unroll
    for (int o = 16; o; o >>= 1) lvar += __shfl_xor_sync(0xffffffffu, lvar, o);
    const float inv = rsqrtf(lvar / (float)D_DIM + 1e-5f);

#pragma unroll
    for (int u = 0; u < D_DIM / 32; u++) {
        int c = lane + 32 * u;
        out[(long)row * D_DIM + c] = (xv[u] - mu) * inv * w[c] + bias[c];
    }
}

// ---------------- launch ----------------
extern "C" void kernel_launch(void* const* d_in, const int* in_sizes, int n_in,
                              void* d_out, int out_size)
{
    float* out = (float*)d_out;

    const long exp_sizes[18] = {
        (long)M_ROWS * D_DIM, (long)M_ROWS * D_DIM, (long)M_ROWS * D_DIM,
        (long)D_DIM * D_DIM, D_DIM,
        (long)D_DIM * D_DIM, D_DIM,
        (long)D_DIM * D_DIM, D_DIM,
        H_DIM,
        D_DIM, D_DIM,
        (long)F_DIM * D_DIM, F_DIM,
        (long)D_DIM * F_DIM, D_DIM,
        D_DIM, D_DIM
    };

    bool ok_e = (n_in >= 18), ok_b = (n_in >= 18);
    for (int idx = 0; idx < 18 && (ok_e || ok_b); idx++) {
        if ((long)in_sizes[idx] != exp_sizes[idx])     ok_e = false;
        if ((long)in_sizes[idx] != exp_sizes[idx] * 4) ok_b = false;
    }
    bool ok = (ok_e || ok_b) &&
              ((long)out_size == (long)M_ROWS * D_DIM ||
               (long)out_size == (long)M_ROWS * D_DIM * 4);
    if (ok) {
        for (int idx = 0; idx < 18; idx++)
            if (((uintptr_t)d_in[idx] & 15u) != 0) { ok = false; break; }
        if (((uintptr_t)d_out & 15u) != 0) ok = false;
    }
    if (!ok) {
        long n = (long)M_ROWS * D_DIM;
        if ((long)out_size < n) n = (long)out_size;
        zero_out_k<<<1024, 256>>>(out, n);
        return;
    }

    const float* query  = (const float*)d_in[0];
    const float* key    = (const float*)d_in[1];
    const float* values = (const float*)d_in[2];
    const float* Wk     = (const float*)d_in[3];
    const float* bk     = (const float*)d_in[4];
    const float* Wv     = (const float*)d_in[5];
    const float* bv     = (const float*)d_in[6];
    const float* Wo     = (const float*)d_in[7];
    const float* bo     = (const float*)d_in[8];
    const float* gammas = (const float*)d_in[9];
    const float* ln1_w  = (const float*)d_in[10];
    const float* ln1_b  = (const float*)d_in[11];
    const float* W1     = (const float*)d_in[12];
    const float* b1     = (const float*)d_in[13];
    const float* W2     = (const float*)d_in[14];
    const float* b2     = (const float*)d_in[15];
    const float* ln2_w  = (const float*)d_in[16];
    const float* ln2_b  = (const float*)d_in[17];

    // mask: python scalar (value 1). NEVER dereference; decode from pointer
    // value only if it is a tiny immediate.
    int mask_val = 1;
    if (n_in >= 19) {
        uintptr_t v = (uintptr_t)d_in[18];
        if (v >= 1 && v < 4096) mask_val = (int)v;
    }

    dim3 gD(D_DIM / 32, M_ROWS / 16);   // (32, 256)
    dim3 gF(F_DIM / 32, M_ROWS / 16);   // (128, 256)

    // q/k/v projections (kq_same: q and k both use Wk)
    gemm_v3<0, -1, 0, D_DIM><<<gD, 256>>>(query,  Wk, bk, nullptr, M_ROWS, D_DIM);
    gemm_v3<0, -1, 1, D_DIM><<<gD, 256>>>(key,    Wk, bk, nullptr, M_ROWS, D_DIM);
    gemm_v3<0, -1, 2, D_DIM><<<gD, 256>>>(values, Wv, bv, nullptr, M_ROWS, D_DIM);

    // transpose K and V per head for coalesced attention reads
    dim3 gT(S_LEN / 256, DK, B_DIM * H_DIM);
    htrans_kernel<1><<<gT, 256>>>();
    htrans_kernel<2><<<gT, 256>>>();

    // attention with distance decay (warp per row, fully coalesced)
    dim3 gA(S_LEN / 8, H_DIM, B_DIM);
    attn_v3<<<gA, 256>>>(gammas, mask_val);

    // output projection + LN1
    gemm_v3<0, 3, 4, D_DIM><<<gD, 256>>>(nullptr, Wo, bo, nullptr, M_ROWS, D_DIM);
    add_ln_ns<-1, 4, 5><<<M_ROWS / 8, 256>>>(query, nullptr, ln1_w, ln1_b, nullptr);

    // FFN + LN2 (final output to d_out)
    gemm_v3<1, 5, 6, D_DIM><<<gF, 256>>>(nullptr, W1, b1, nullptr, M_ROWS, F_DIM);
    gemm_v3<0, 6, 7, F_DIM><<<gD, 256>>>(nullptr, W2, b2, nullptr, M_ROWS, D_DIM);
    add_ln_ns<5, 7, -1><<<M_ROWS / 8, 256>>>(nullptr, nullptr, ln2_w, ln2_b, out);
}

// round 16
// speedup vs baseline: 16.0265x; 1.5819x over previous
#include <cuda_runtime.h>
#include <math.h>
#include <stdint.h>

// ---------------- problem constants ----------------
#define S_LEN 2048
#define D_DIM 1024
#define B_DIM 2
#define H_DIM 16
#define DK    64
#define F_DIM 4096
#define M_ROWS (B_DIM * S_LEN)   // 4096

// ---------------- scratch (static device globals; no allocation) -----------
__device__ __align__(256) float g_qb[M_ROWS * D_DIM];
__device__ __align__(256) float g_kb[M_ROWS * D_DIM];
__device__ __align__(256) float g_vb[M_ROWS * D_DIM];
__device__ __align__(256) float g_kT[B_DIM * H_DIM * DK * S_LEN];  // [b,h,c,j]
__device__ __align__(256) float g_concat[M_ROWS * D_DIM];
__device__ __align__(256) float g_q2[M_ROWS * D_DIM];
__device__ __align__(256) float g_x1[M_ROWS * D_DIM];
__device__ __align__(256) float g_h1[M_ROWS * F_DIM];
__device__ __align__(256) float g_ff[M_ROWS * D_DIM];

template <int ID>
__device__ __forceinline__ float* gsel(float* ext) {
    if (ID == 0) return g_qb;
    if (ID == 1) return g_kb;
    if (ID == 2) return g_vb;
    if (ID == 3) return g_concat;
    if (ID == 4) return g_q2;
    if (ID == 5) return g_x1;
    if (ID == 6) return g_h1;
    if (ID == 7) return g_ff;
    return ext;
}

// ---------------- fallback ----------------
__global__ void zero_out_k(float* out, long n) {
    long idx = (long)blockIdx.x * blockDim.x + threadIdx.x;
    for (; idx < n; idx += (long)gridDim.x * blockDim.x) out[idx] = 0.f;
}

// ================= GEMM v3 (256 threads — the PROVEN R12/R13 version) ======
// REGISTER LEDGER (do not violate): acc 64 + cur bufs 64 + next bufs 64
// + addressing ~= 220 regs. Needs 256 threads/block (255-reg cap). 512
// threads (R14) forced 128-reg cap -> spills -> 15x regression.
template <int RELU, int AID, int CID, int KT>
__global__ void __launch_bounds__(256) gemm_v3(
    const float* __restrict__ Aext, const float* __restrict__ Wm,
    const float* __restrict__ bias, float* __restrict__ Cext,
    int M, int N)
{
    const float* A = gsel<AID>((float*)Aext);
    float* C = gsel<CID>(Cext);

    const int tid  = threadIdx.x;
    const int warp = tid >> 5;
    const int lane = tid & 31;
    const int wr = warp >> 2;
    const int wc = warp & 3;
    const int r0 = blockIdx.y * 16 + wr * 8;
    const int c0 = blockIdx.x * 32 + wc * 8;

    const float* Ab = A + (long)r0 * KT + lane * 4;
    const float* Wb = Wm + (long)c0 * KT + lane * 4;

    float acc[8][8];
#pragma unroll
    for (int r = 0; r < 8; r++)
#pragma unroll
        for (int c = 0; c < 8; c++) acc[r][c] = 0.f;

    float4 aC[8], wC[8];
#pragma unroll
    for (int r = 0; r < 8; r++) aC[r] = *(const float4*)(Ab + (long)r * KT);
#pragma unroll
    for (int c = 0; c < 8; c++) wC[c] = *(const float4*)(Wb + (long)c * KT);

#pragma unroll 2
    for (int k0 = 128; k0 <= KT; k0 += 128) {
        float4 aN[8], wN[8];
        const bool more = (k0 < KT);
        if (more) {
#pragma unroll
            for (int r = 0; r < 8; r++)
                aN[r] = *(const float4*)(Ab + (long)r * KT + k0);
#pragma unroll
            for (int c = 0; c < 8; c++)
                wN[c] = *(const float4*)(Wb + (long)c * KT + k0);
        }
#pragma unroll
        for (int r = 0; r < 8; r++)
#pragma unroll
            for (int c = 0; c < 8; c++) {
                float t = acc[r][c];
                t = fmaf(aC[r].x, wC[c].x, t);
                t = fmaf(aC[r].y, wC[c].y, t);
                t = fmaf(aC[r].z, wC[c].z, t);
                t = fmaf(aC[r].w, wC[c].w, t);
                acc[r][c] = t;
            }
        if (more) {
#pragma unroll
            for (int r = 0; r < 8; r++) aC[r] = aN[r];
#pragma unroll
            for (int c = 0; c < 8; c++) wC[c] = wN[c];
        }
    }

#pragma unroll
    for (int r = 0; r < 8; r++)
#pragma unroll
        for (int c = 0; c < 8; c++) {
#pragma unroll
            for (int o = 16; o; o >>= 1)
                acc[r][c] += __shfl_xor_sync(0xffffffffu, acc[r][c], o);
        }

#pragma unroll
    for (int u = 0; u < 2; u++) {
        int o = lane + 32 * u;
        int r = o >> 3, c = o & 7;
        float x = acc[r][c] + bias[c0 + c];
        if (RELU) x = fmaxf(x, 0.f);
        C[(long)(r0 + r) * N + c0 + c] = x;
    }
}

// ================= K transpose: g_kb[b,j,(h,c)] -> g_kT[b,h,c,j] ===========
__global__ void __launch_bounds__(256) ktrans_kernel()
{
    const int j  = blockIdx.x * 256 + threadIdx.x;
    const int c  = blockIdx.y;
    const int bh = blockIdx.z;
    const int b = bh >> 4, h = bh & 15;
    float v = g_kb[(long)b * S_LEN * D_DIM + (long)j * D_DIM + h * DK + c];
    g_kT[((long)bh * DK + c) * S_LEN + j] = v;
}

// ================= ATTENTION v2 (R13-proven) + split AV chains =============
// One warp per (query row i, head h, batch b). Lane owns j = chunk*32+lane.
// K loads via g_kT (coalesced). AV pass: shfl-broadcast weights, V[j][lane]
// coalesced; accumulators split even/odd jj to halve the FFMA dep chain.
// REGISTER LEDGER: peak live = sl[64] + q[64] (pass 1 only) ~ 146 regs. Do
// NOT hold a second 64-float array live with sl (R15 spill lesson).
__global__ void __launch_bounds__(256) attn_v2(
    const float* __restrict__ gammas, int mask_val)
{
    const int tid  = threadIdx.x;
    const int warp = tid >> 5;
    const int lane = tid & 31;
    const int i = blockIdx.x * 8 + warp;
    const int h = blockIdx.y;
    const int b = blockIdx.z;

    const int L = min(S_LEN, i + mask_val);
    const int nch = (L + 31) >> 5;

    const float* kT = g_kT + (long)(b * H_DIM + h) * DK * S_LEN;
    const long qoff = (long)b * S_LEN * D_DIM + (long)i * D_DIM + h * DK;

    float q[DK];
#pragma unroll
    for (int c = 0; c < DK; c++) q[c] = g_qb[qoff + c];

    float sl[S_LEN / 32];

    // ---- pass 1: scores (coalesced K reads) ----
    for (int ch = 0; ch < nch; ch++) {
        const int j = ch * 32 + lane;
        float acc = 0.f;
#pragma unroll
        for (int c = 0; c < DK; c++)
            acc = fmaf(q[c], kT[(long)c * S_LEN + j], acc);
        sl[ch] = (j < L) ? acc * 0.125f : -INFINITY;
    }

    // ---- softmax #1 stats ----
    float m1 = -INFINITY;
    for (int ch = 0; ch < nch; ch++) m1 = fmaxf(m1, sl[ch]);
#pragma unroll
    for (int o = 16; o; o >>= 1) m1 = fmaxf(m1, __shfl_xor_sync(0xffffffffu, m1, o));
    float zs = 0.f;
    for (int ch = 0; ch < nch; ch++) zs += __expf(sl[ch] - m1);
#pragma unroll
    for (int o = 16; o; o >>= 1) zs += __shfl_xor_sync(0xffffffffu, zs, o);
    const float Zinv = 1.f / zs;

    // ---- pass 2: ordered cumsum + distance decay ----
    const float gv = gammas[h];
    const float gamma = -(gv > 20.f ? gv : log1pf(__expf(gv)));
    float running = 0.f;
    float m2 = -INFINITY;
    for (int ch = 0; ch < nch; ch++) {
        float p = __expf(sl[ch] - m1);
        float incl = p;
#pragma unroll
        for (int o = 1; o < 32; o <<= 1) {
            float t = __shfl_up_sync(0xffffffffu, incl, o);
            if (lane >= o) incl += t;
        }
        const int j = ch * 32 + lane;
        float sd = -INFINITY;
        if (j < L) {
            float ctot = (running + incl) * Zinv;
            float pe = fabsf((float)(i - j));
            float ds = sqrtf(fmaxf((1.f - ctot) * pe, 0.f));
            float te = fmaxf(__expf(gamma * ds), 1e-5f);
            sd = sl[ch] * te;
        }
        sl[ch] = sd;
        m2 = fmaxf(m2, sd);
        running += __shfl_sync(0xffffffffu, incl, 31);
    }

    // ---- softmax #2 stats ----
#pragma unroll
    for (int o = 16; o; o >>= 1) m2 = fmaxf(m2, __shfl_xor_sync(0xffffffffu, m2, o));
    float z2 = 0.f;
    for (int ch = 0; ch < nch; ch++) z2 += __expf(sl[ch] - m2);
#pragma unroll
    for (int o = 16; o; o >>= 1) z2 += __shfl_xor_sync(0xffffffffu, z2, o);
    const float Z2inv = 1.f / z2;

    // ---- pass 3: out = attn @ V (broadcast weights; split dep chains) ----
    const float* Vb = g_vb + (long)b * S_LEN * D_DIM + h * DK;
    float ov0a = 0.f, ov0b = 0.f, ov1a = 0.f, ov1b = 0.f;
    for (int ch = 0; ch < nch; ch++) {
        float wl = __expf(sl[ch] - m2) * Z2inv;
#pragma unroll 8
        for (int jj = 0; jj < 32; jj += 2) {
            float wj0 = __shfl_sync(0xffffffffu, wl, jj);
            float wj1 = __shfl_sync(0xffffffffu, wl, jj + 1);
            const float* vr0 = Vb + (long)(ch * 32 + jj) * D_DIM;
            const float* vr1 = vr0 + D_DIM;
            ov0a = fmaf(wj0, vr0[lane], ov0a);
            ov1a = fmaf(wj0, vr0[lane + 32], ov1a);
            ov0b = fmaf(wj1, vr1[lane], ov0b);
            ov1b = fmaf(wj1, vr1[lane + 32], ov1b);
        }
    }

    g_concat[(long)(b * S_LEN + i) * D_DIM + h * DK + lane]      = ov0a + ov0b;
    g_concat[(long)(b * S_LEN + i) * D_DIM + h * DK + lane + 32] = ov1a + ov1b;
}

// ============ residual add + LayerNorm (unchanged) =========================
template <int XID, int YID, int OID>
__global__ void __launch_bounds__(256) add_ln_ns(
    const float* __restrict__ Xext, const float* __restrict__ Yext,
    const float* __restrict__ w, const float* __restrict__ bias,
    float* __restrict__ Oext)
{
    const float* X = gsel<XID>((float*)Xext);
    const float* Y = gsel<YID>((float*)Yext);
    float* out = gsel<OID>(Oext);

    const int tid  = threadIdx.x;
    const int warp = tid >> 5;
    const int lane = tid & 31;
    const int row = blockIdx.x * 8 + warp;

    float xv[D_DIM / 32];
    float lsum = 0.f;
#pragma unroll
    for (int u = 0; u < D_DIM / 32; u++) {
        int c = lane + 32 * u;
        float v = X[(long)row * D_DIM + c] + Y[(long)row * D_DIM + c];
        xv[u] = v;
        lsum += v;
    }
#pragma unroll
    for (int o = 16; o; o >>= 1) lsum += __shfl_xor_sync(0xffffffffu, lsum, o);
    const float mu = lsum / (float)D_DIM;

    float lvar = 0.f;
#pragma unroll
    for (int u = 0; u < D_DIM / 32; u++) {
        float d = xv[u] - mu;
        lvar += d * d;
    }
#pragma unroll
    for (int o = 16; o; o >>= 1) lvar += __shfl_xor_sync(0xffffffffu, lvar, o);
    const float inv = rsqrtf(lvar / (float)D_DIM + 1e-5f);

#pragma unroll
    for (int u = 0; u < D_DIM / 32; u++) {
        int c = lane + 32 * u;
        out[(long)row * D_DIM + c] = (xv[u] - mu) * inv * w[c] + bias[c];
    }
}

// ---------------- launch ----------------
extern "C" void kernel_launch(void* const* d_in, const int* in_sizes, int n_in,
                              void* d_out, int out_size)
{
    float* out = (float*)d_out;

    const long exp_sizes[18] = {
        (long)M_ROWS * D_DIM, (long)M_ROWS * D_DIM, (long)M_ROWS * D_DIM,
        (long)D_DIM * D_DIM, D_DIM,
        (long)D_DIM * D_DIM, D_DIM,
        (long)D_DIM * D_DIM, D_DIM,
        H_DIM,
        D_DIM, D_DIM,
        (long)F_DIM * D_DIM, F_DIM,
        (long)D_DIM * F_DIM, D_DIM,
        D_DIM, D_DIM
    };

    bool ok_e = (n_in >= 18), ok_b = (n_in >= 18);
    for (int idx = 0; idx < 18 && (ok_e || ok_b); idx++) {
        if ((long)in_sizes[idx] != exp_sizes[idx])     ok_e = false;
        if ((long)in_sizes[idx] != exp_sizes[idx] * 4) ok_b = false;
    }
    bool ok = (ok_e || ok_b) &&
              ((long)out_size == (long)M_ROWS * D_DIM ||
               (long)out_size == (long)M_ROWS * D_DIM * 4);
    if (ok) {
        for (int idx = 0; idx < 18; idx++)
            if (((uintptr_t)d_in[idx] & 15u) != 0) { ok = false; break; }
        if (((uintptr_t)d_out & 15u) != 0) ok = false;
    }
    if (!ok) {
        long n = (long)M_ROWS * D_DIM;
        if ((long)out_size < n) n = (long)out_size;
        zero_out_k<<<1024, 256>>>(out, n);
        return;
    }

    const float* query  = (const float*)d_in[0];
    const float* key    = (const float*)d_in[1];
    const float* values = (const float*)d_in[2];
    const float* Wk     = (const float*)d_in[3];
    const float* bk     = (const float*)d_in[4];
    const float* Wv     = (const float*)d_in[5];
    const float* bv     = (const float*)d_in[6];
    const float* Wo     = (const float*)d_in[7];
    const float* bo     = (const float*)d_in[8];
    const float* gammas = (const float*)d_in[9];
    const float* ln1_w  = (const float*)d_in[10];
    const float* ln1_b  = (const float*)d_in[11];
    const float* W1     = (const float*)d_in[12];
    const float* b1     = (const float*)d_in[13];
    const float* W2     = (const float*)d_in[14];
    const float* b2     = (const float*)d_in[15];
    const float* ln2_w  = (const float*)d_in[16];
    const float* ln2_b  = (const float*)d_in[17];

    // mask: python scalar (value 1). NEVER dereference; decode from pointer
    // value only if it is a tiny immediate.
    int mask_val = 1;
    if (n_in >= 19) {
        uintptr_t v = (uintptr_t)d_in[18];
        if (v >= 1 && v < 4096) mask_val = (int)v;
    }

    dim3 gD(D_DIM / 32, M_ROWS / 16);   // (32, 256)
    dim3 gF(F_DIM / 32, M_ROWS / 16);   // (128, 256)

    // q/k/v projections (kq_same: q and k both use Wk)
    gemm_v3<0, -1, 0, D_DIM><<<gD, 256>>>(query,  Wk, bk, nullptr, M_ROWS, D_DIM);
    gemm_v3<0, -1, 1, D_DIM><<<gD, 256>>>(key,    Wk, bk, nullptr, M_ROWS, D_DIM);
    gemm_v3<0, -1, 2, D_DIM><<<gD, 256>>>(values, Wv, bv, nullptr, M_ROWS, D_DIM);

    // transpose K per head for coalesced attention reads
    dim3 gT(S_LEN / 256, DK, B_DIM * H_DIM);
    ktrans_kernel<<<gT, 256>>>();

    // attention with distance decay (warp per row, coalesced)
    dim3 gA(S_LEN / 8, H_DIM, B_DIM);
    attn_v2<<<gA, 256>>>(gammas, mask_val);

    // output projection + LN1
    gemm_v3<0, 3, 4, D_DIM><<<gD, 256>>>(nullptr, Wo, bo, nullptr, M_ROWS, D_DIM);
    add_ln_ns<-1, 4, 5><<<M_ROWS / 8, 256>>>(query, nullptr, ln1_w, ln1_b, nullptr);

    // FFN + LN2 (final output to d_out)
    gemm_v3<1, 5, 6, D_DIM><<<gF, 256>>>(nullptr, W1, b1, nullptr, M_ROWS, F_DIM);
    gemm_v3<0, 6, 7, F_DIM><<<gD, 256>>>(nullptr, W2, b2, nullptr, M_ROWS, D_DIM);
    add_ln_ns<5, 7, -1><<<M_ROWS / 8, 256>>>(nullptr, nullptr, ln2_w, ln2_b, out);
}

// round 17
// speedup vs baseline: 16.4484x; 1.0263x over previous
#include <cuda_runtime.h>
#include <math.h>
#include <stdint.h>

// ---------------- problem constants ----------------
#define S_LEN 2048
#define D_DIM 1024
#define B_DIM 2
#define H_DIM 16
#define DK    64
#define F_DIM 4096
#define M_ROWS (B_DIM * S_LEN)   // 4096

// ---------------- scratch (static device globals; no allocation) -----------
__device__ __align__(256) float g_qb[M_ROWS * D_DIM];
__device__ __align__(256) float g_kb[M_ROWS * D_DIM];
__device__ __align__(256) float g_vb[M_ROWS * D_DIM];
__device__ __align__(256) float g_kT[B_DIM * H_DIM * DK * S_LEN];  // [b,h,c,j]
__device__ __align__(256) float g_concat[M_ROWS * D_DIM];
__device__ __align__(256) float g_q2[M_ROWS * D_DIM];
__device__ __align__(256) float g_x1[M_ROWS * D_DIM];
__device__ __align__(256) float g_h1[M_ROWS * F_DIM];
__device__ __align__(256) float g_ff[M_ROWS * D_DIM];

template <int ID>
__device__ __forceinline__ float* gsel(float* ext) {
    if (ID == 0) return g_qb;
    if (ID == 1) return g_kb;
    if (ID == 2) return g_vb;
    if (ID == 3) return g_concat;
    if (ID == 4) return g_q2;
    if (ID == 5) return g_x1;
    if (ID == 6) return g_h1;
    if (ID == 7) return g_ff;
    return ext;
}

// ---------------- fallback ----------------
__global__ void zero_out_k(float* out, long n) {
    long idx = (long)blockIdx.x * blockDim.x + threadIdx.x;
    for (; idx < n; idx += (long)gridDim.x * blockDim.x) out[idx] = 0.f;
}

// ================= GEMM v3 (256 threads — PROVEN; unchanged) ===============
// REGISTER LEDGER: acc 64 + bufs 128 + addressing ~= 220 regs; needs the
// 255-reg cap of 256 threads. (R14: 512 threads -> 128-reg cap -> 15x slow.)
template <int RELU, int AID, int CID, int KT>
__global__ void __launch_bounds__(256) gemm_v3(
    const float* __restrict__ Aext, const float* __restrict__ Wm,
    const float* __restrict__ bias, float* __restrict__ Cext,
    int M, int N)
{
    const float* A = gsel<AID>((float*)Aext);
    float* C = gsel<CID>(Cext);

    const int tid  = threadIdx.x;
    const int warp = tid >> 5;
    const int lane = tid & 31;
    const int wr = warp >> 2;
    const int wc = warp & 3;
    const int r0 = blockIdx.y * 16 + wr * 8;
    const int c0 = blockIdx.x * 32 + wc * 8;

    const float* Ab = A + (long)r0 * KT + lane * 4;
    const float* Wb = Wm + (long)c0 * KT + lane * 4;

    float acc[8][8];
#pragma unroll
    for (int r = 0; r < 8; r++)
#pragma unroll
        for (int c = 0; c < 8; c++) acc[r][c] = 0.f;

    float4 aC[8], wC[8];
#pragma unroll
    for (int r = 0; r < 8; r++) aC[r] = *(const float4*)(Ab + (long)r * KT);
#pragma unroll
    for (int c = 0; c < 8; c++) wC[c] = *(const float4*)(Wb + (long)c * KT);

#pragma unroll 2
    for (int k0 = 128; k0 <= KT; k0 += 128) {
        float4 aN[8], wN[8];
        const bool more = (k0 < KT);
        if (more) {
#pragma unroll
            for (int r = 0; r < 8; r++)
                aN[r] = *(const float4*)(Ab + (long)r * KT + k0);
#pragma unroll
            for (int c = 0; c < 8; c++)
                wN[c] = *(const float4*)(Wb + (long)c * KT + k0);
        }
#pragma unroll
        for (int r = 0; r < 8; r++)
#pragma unroll
            for (int c = 0; c < 8; c++) {
                float t = acc[r][c];
                t = fmaf(aC[r].x, wC[c].x, t);
                t = fmaf(aC[r].y, wC[c].y, t);
                t = fmaf(aC[r].z, wC[c].z, t);
                t = fmaf(aC[r].w, wC[c].w, t);
                acc[r][c] = t;
            }
        if (more) {
#pragma unroll
            for (int r = 0; r < 8; r++) aC[r] = aN[r];
#pragma unroll
            for (int c = 0; c < 8; c++) wC[c] = wN[c];
        }
    }

#pragma unroll
    for (int r = 0; r < 8; r++)
#pragma unroll
        for (int c = 0; c < 8; c++) {
#pragma unroll
            for (int o = 16; o; o >>= 1)
                acc[r][c] += __shfl_xor_sync(0xffffffffu, acc[r][c], o);
        }

#pragma unroll
    for (int u = 0; u < 2; u++) {
        int o = lane + 32 * u;
        int r = o >> 3, c = o & 7;
        float x = acc[r][c] + bias[c0 + c];
        if (RELU) x = fmaxf(x, 0.f);
        C[(long)(r0 + r) * N + c0 + c] = x;
    }
}

// ================= K transpose: g_kb[b,j,(h,c)] -> g_kT[b,h,c,j] ===========
__global__ void __launch_bounds__(256) ktrans_kernel()
{
    const int j  = blockIdx.x * 256 + threadIdx.x;
    const int c  = blockIdx.y;
    const int bh = blockIdx.z;
    const int b = bh >> 4, h = bh & 15;
    float v = g_kb[(long)b * S_LEN * D_DIM + (long)j * D_DIM + h * DK + c];
    g_kT[((long)bh * DK + c) * S_LEN + j] = v;
}

// ================= ATTENTION v5: float4 loads, 4x fewer LDG ================
// One warp per (query row i, head h, batch b). Superchunk = 128 j's; lane
// owns j = sc*128 + 4*lane + t (t=0..3) — monotone ordering for the cumsum.
// Pass 1: K via float4 from kT.  Pass 3: half-warps cover 2 j's per LDG.128
// of V (jsel = lane>>4), weights shfl-broadcast, chains split.
// REGISTER LEDGER: peak live = q[64] + sl[64] + ~20 ~= 150 regs (<255). Do
// NOT add another 64-float array live with sl (R15 lesson).
__global__ void __launch_bounds__(256) attn_v5(
    const float* __restrict__ gammas, int mask_val)
{
    const int tid  = threadIdx.x;
    const int warp = tid >> 5;
    const int lane = tid & 31;
    const int i = blockIdx.x * 8 + warp;
    const int h = blockIdx.y;
    const int b = blockIdx.z;

    const int L = min(S_LEN, i + mask_val);
    const int nsc = (L + 127) >> 7;            // superchunks of 128

    const float* kT = g_kT + (long)(b * H_DIM + h) * DK * S_LEN;
    const long qoff = (long)b * S_LEN * D_DIM + (long)i * D_DIM + h * DK;

    float q[DK];
#pragma unroll
    for (int c4 = 0; c4 < 16; c4++) {
        float4 t = *(const float4*)(g_qb + qoff + c4 * 4);
        q[4 * c4 + 0] = t.x; q[4 * c4 + 1] = t.y;
        q[4 * c4 + 2] = t.z; q[4 * c4 + 3] = t.w;
    }

    float sl[S_LEN / 32];   // sl[4*sc + t] is j = sc*128 + 4*lane + t

    // ---- pass 1: scores via float4 K reads ----
    for (int sc = 0; sc < nsc; sc++) {
        float a0 = 0.f, a1 = 0.f, a2 = 0.f, a3 = 0.f;
        const float* kp = kT + sc * 128 + lane * 4;
#pragma unroll
        for (int c = 0; c < DK; c++) {
            float4 kv = *(const float4*)(kp + (long)c * S_LEN);
            a0 = fmaf(q[c], kv.x, a0);
            a1 = fmaf(q[c], kv.y, a1);
            a2 = fmaf(q[c], kv.z, a2);
            a3 = fmaf(q[c], kv.w, a3);
        }
        const int j0 = sc * 128 + lane * 4;
        sl[4 * sc + 0] = (j0 + 0 < L) ? a0 * 0.125f : -INFINITY;
        sl[4 * sc + 1] = (j0 + 1 < L) ? a1 * 0.125f : -INFINITY;
        sl[4 * sc + 2] = (j0 + 2 < L) ? a2 * 0.125f : -INFINITY;
        sl[4 * sc + 3] = (j0 + 3 < L) ? a3 * 0.125f : -INFINITY;
    }

    // ---- softmax #1 stats ----
    float m1 = -INFINITY;
    for (int sc = 0; sc < nsc; sc++) {
#pragma unroll
        for (int t = 0; t < 4; t++) m1 = fmaxf(m1, sl[4 * sc + t]);
    }
#pragma unroll
    for (int o = 16; o; o >>= 1) m1 = fmaxf(m1, __shfl_xor_sync(0xffffffffu, m1, o));
    float zs = 0.f;
    for (int sc = 0; sc < nsc; sc++) {
#pragma unroll
        for (int t = 0; t < 4; t++) zs += __expf(sl[4 * sc + t] - m1);
    }
#pragma unroll
    for (int o = 16; o; o >>= 1) zs += __shfl_xor_sync(0xffffffffu, zs, o);
    const float Zinv = 1.f / zs;

    // ---- pass 2: ordered cumsum + distance decay ----
    const float gv = gammas[h];
    const float gamma = -(gv > 20.f ? gv : log1pf(__expf(gv)));  // -softplus<0
    float running = 0.f;
    float m2 = -INFINITY;
    for (int sc = 0; sc < nsc; sc++) {
        float p0 = __expf(sl[4 * sc + 0] - m1);
        float p1 = __expf(sl[4 * sc + 1] - m1);
        float p2 = __expf(sl[4 * sc + 2] - m1);
        float p3 = __expf(sl[4 * sc + 3] - m1);
        float lt = p0 + p1 + p2 + p3;           // lane total
        float incl = lt;
#pragma unroll
        for (int o = 1; o < 32; o <<= 1) {
            float t = __shfl_up_sync(0xffffffffu, incl, o);
            if (lane >= o) incl += t;
        }
        const float base = running + (incl - lt);
        float cum[4];
        cum[0] = base + p0;
        cum[1] = cum[0] + p1;
        cum[2] = cum[1] + p2;
        cum[3] = cum[2] + p3;
        const int j0 = sc * 128 + lane * 4;
#pragma unroll
        for (int t = 0; t < 4; t++) {
            const int j = j0 + t;
            float sd = -INFINITY;
            if (j < L) {
                float ctot = cum[t] * Zinv;
                float pe = fabsf((float)(i - j));
                float ds = sqrtf(fmaxf((1.f - ctot) * pe, 0.f));
                float te = fmaxf(__expf(gamma * ds), 1e-5f);
                sd = sl[4 * sc + t] * te;
            }
            sl[4 * sc + t] = sd;
            m2 = fmaxf(m2, sd);
        }
        running += __shfl_sync(0xffffffffu, incl, 31);
    }

    // ---- softmax #2 stats ----
#pragma unroll
    for (int o = 16; o; o >>= 1) m2 = fmaxf(m2, __shfl_xor_sync(0xffffffffu, m2, o));
    float z2 = 0.f;
    for (int sc = 0; sc < nsc; sc++) {
#pragma unroll
        for (int t = 0; t < 4; t++) z2 += __expf(sl[4 * sc + t] - m2);
    }
#pragma unroll
    for (int o = 16; o; o >>= 1) z2 += __shfl_xor_sync(0xffffffffu, z2, o);
    const float Z2inv = 1.f / z2;

    // ---- pass 3: out = attn @ V via float4, half-warp j-split ----
    const float* Vb = g_vb + (long)b * S_LEN * D_DIM + h * DK;
    const int jsel = lane >> 4;          // 0 or 1
    const int c4 = (lane & 15) * 4;      // this lane's 4 output dims
    float oA0 = 0.f, oA1 = 0.f, oA2 = 0.f, oA3 = 0.f;
    float oB0 = 0.f, oB1 = 0.f, oB2 = 0.f, oB3 = 0.f;
    for (int sc = 0; sc < nsc; sc++) {
        float w0 = __expf(sl[4 * sc + 0] - m2) * Z2inv;
        float w1 = __expf(sl[4 * sc + 1] - m2) * Z2inv;
        float w2 = __expf(sl[4 * sc + 2] - m2) * Z2inv;
        float w3 = __expf(sl[4 * sc + 3] - m2) * Z2inv;
        const float* Vsc = Vb + (long)(sc * 128) * D_DIM + c4;
#pragma unroll 8
        for (int g = 0; g < 32; g++) {
            // lane g owns j = sc*128 + 4g + t
            float wA0 = __shfl_sync(0xffffffffu, w0, g);
            float wA1 = __shfl_sync(0xffffffffu, w1, g);
            float wB0 = __shfl_sync(0xffffffffu, w2, g);
            float wB1 = __shfl_sync(0xffffffffu, w3, g);
            const float* pA = Vsc + (long)(4 * g + jsel) * D_DIM;
            const float* pB = pA + 2 * D_DIM;
            float4 vA = *(const float4*)pA;
            float4 vB = *(const float4*)pB;
            float wA = jsel ? wA1 : wA0;
            float wB = jsel ? wB1 : wB0;
            oA0 = fmaf(wA, vA.x, oA0); oA1 = fmaf(wA, vA.y, oA1);
            oA2 = fmaf(wA, vA.z, oA2); oA3 = fmaf(wA, vA.w, oA3);
            oB0 = fmaf(wB, vB.x, oB0); oB1 = fmaf(wB, vB.y, oB1);
            oB2 = fmaf(wB, vB.z, oB2); oB3 = fmaf(wB, vB.w, oB3);
        }
    }
    float o0 = oA0 + oB0, o1 = oA1 + oB1, o2 = oA2 + oB2, o3 = oA3 + oB3;
    // combine the two half-warps (lane ^ 16 holds the other jsel's partials)
    o0 += __shfl_xor_sync(0xffffffffu, o0, 16);
    o1 += __shfl_xor_sync(0xffffffffu, o1, 16);
    o2 += __shfl_xor_sync(0xffffffffu, o2, 16);
    o3 += __shfl_xor_sync(0xffffffffu, o3, 16);

    if (lane < 16) {
        float4 ov = make_float4(o0, o1, o2, o3);
        *(float4*)(g_concat + (long)(b * S_LEN + i) * D_DIM + h * DK + c4) = ov;
    }
}

// ============ residual add + LayerNorm (unchanged) =========================
template <int XID, int YID, int OID>
__global__ void __launch_bounds__(256) add_ln_ns(
    const float* __restrict__ Xext, const float* __restrict__ Yext,
    const float* __restrict__ w, const float* __restrict__ bias,
    float* __restrict__ Oext)
{
    const float* X = gsel<XID>((float*)Xext);
    const float* Y = gsel<YID>((float*)Yext);
    float* out = gsel<OID>(Oext);

    const int tid  = threadIdx.x;
    const int warp = tid >> 5;
    const int lane = tid & 31;
    const int row = blockIdx.x * 8 + warp;

    float xv[D_DIM / 32];
    float lsum = 0.f;
#pragma unroll
    for (int u = 0; u < D_DIM / 32; u++) {
        int c = lane + 32 * u;
        float v = X[(long)row * D_DIM + c] + Y[(long)row * D_DIM + c];
        xv[u] = v;
        lsum += v;
    }
#pragma unroll
    for (int o = 16; o; o >>= 1) lsum += __shfl_xor_sync(0xffffffffu, lsum, o);
    const float mu = lsum / (float)D_DIM;

    float lvar = 0.f;
#pragma unroll
    for (int u = 0; u < D_DIM / 32; u++) {
        float d = xv[u] - mu;
        lvar += d * d;
    }
#pragma unroll
    for (int o = 16; o; o >>= 1) lvar += __shfl_xor_sync(0xffffffffu, lvar, o);
    const float inv = rsqrtf(lvar / (float)D_DIM + 1e-5f);

#pragma unroll
    for (int u = 0; u < D_DIM / 32; u++) {
        int c = lane + 32 * u;
        out[(long)row * D_DIM + c] = (xv[u] - mu) * inv * w[c] + bias[c];
    }
}

// ---------------- launch ----------------
extern "C" void kernel_launch(void* const* d_in, const int* in_sizes, int n_in,
                              void* d_out, int out_size)
{
    float* out = (float*)d_out;

    const long exp_sizes[18] = {
        (long)M_ROWS * D_DIM, (long)M_ROWS * D_DIM, (long)M_ROWS * D_DIM,
        (long)D_DIM * D_DIM, D_DIM,
        (long)D_DIM * D_DIM, D_DIM,
        (long)D_DIM * D_DIM, D_DIM,
        H_DIM,
        D_DIM, D_DIM,
        (long)F_DIM * D_DIM, F_DIM,
        (long)D_DIM * F_DIM, D_DIM,
        D_DIM, D_DIM
    };

    bool ok_e = (n_in >= 18), ok_b = (n_in >= 18);
    for (int idx = 0; idx < 18 && (ok_e || ok_b); idx++) {
        if ((long)in_sizes[idx] != exp_sizes[idx])     ok_e = false;
        if ((long)in_sizes[idx] != exp_sizes[idx] * 4) ok_b = false;
    }
    bool ok = (ok_e || ok_b) &&
              ((long)out_size == (long)M_ROWS * D_DIM ||
               (long)out_size == (long)M_ROWS * D_DIM * 4);
    if (ok) {
        for (int idx = 0; idx < 18; idx++)
            if (((uintptr_t)d_in[idx] & 15u) != 0) { ok = false; break; }
        if (((uintptr_t)d_out & 15u) != 0) ok = false;
    }
    if (!ok) {
        long n = (long)M_ROWS * D_DIM;
        if ((long)out_size < n) n = (long)out_size;
        zero_out_k<<<1024, 256>>>(out, n);
        return;
    }

    const float* query  = (const float*)d_in[0];
    const float* key    = (const float*)d_in[1];
    const float* values = (const float*)d_in[2];
    const float* Wk     = (const float*)d_in[3];
    const float* bk     = (const float*)d_in[4];
    const float* Wv     = (const float*)d_in[5];
    const float* bv     = (const float*)d_in[6];
    const float* Wo     = (const float*)d_in[7];
    const float* bo     = (const float*)d_in[8];
    const float* gammas = (const float*)d_in[9];
    const float* ln1_w  = (const float*)d_in[10];
    const float* ln1_b  = (const float*)d_in[11];
    const float* W1     = (const float*)d_in[12];
    const float* b1     = (const float*)d_in[13];
    const float* W2     = (const float*)d_in[14];
    const float* b2     = (const float*)d_in[15];
    const float* ln2_w  = (const float*)d_in[16];
    const float* ln2_b  = (const float*)d_in[17];

    // mask: python scalar (value 1). NEVER dereference; decode from pointer
    // value only if it is a tiny immediate.
    int mask_val = 1;
    if (n_in >= 19) {
        uintptr_t v = (uintptr_t)d_in[18];
        if (v >= 1 && v < 4096) mask_val = (int)v;
    }

    dim3 gD(D_DIM / 32, M_ROWS / 16);   // (32, 256)
    dim3 gF(F_DIM / 32, M_ROWS / 16);   // (128, 256)

    // q/k/v projections (kq_same: q and k both use Wk)
    gemm_v3<0, -1, 0, D_DIM><<<gD, 256>>>(query,  Wk, bk, nullptr, M_ROWS, D_DIM);
    gemm_v3<0, -1, 1, D_DIM><<<gD, 256>>>(key,    Wk, bk, nullptr, M_ROWS, D_DIM);
    gemm_v3<0, -1, 2, D_DIM><<<gD, 256>>>(values, Wv, bv, nullptr, M_ROWS, D_DIM);

    // transpose K per head for coalesced attention reads
    dim3 gT(S_LEN / 256, DK, B_DIM * H_DIM);
    ktrans_kernel<<<gT, 256>>>();

    // attention with distance decay (warp per row, float4 loads)
    dim3 gA(S_LEN / 8, H_DIM, B_DIM);
    attn_v5<<<gA, 256>>>(gammas, mask_val);

    // output projection + LN1
    gemm_v3<0, 3, 4, D_DIM><<<gD, 256>>>(nullptr, Wo, bo, nullptr, M_ROWS, D_DIM);
    add_ln_ns<-1, 4, 5><<<M_ROWS / 8, 256>>>(query, nullptr, ln1_w, ln1_b, nullptr);

    // FFN + LN2 (final output to d_out)
    gemm_v3<1, 5, 6, D_DIM><<<gF, 256>>>(nullptr, W1, b1, nullptr, M_ROWS, F_DIM);
    gemm_v3<0, 6, 7, F_DIM><<<gD, 256>>>(nullptr, W2, b2, nullptr, M_ROWS, D_DIM);
    add_ln_ns<5, 7, -1><<<M_ROWS / 8, 256>>>(nullptr, nullptr, ln2_w, ln2_b, out);
}